// round 14
// baseline (speedup 1.0000x reference)
#include <cuda_runtime.h>
#include <cuda_fp16.h>
#include <cstddef>
#include <cstdint>

// Problem constants (fixed shapes from reference)
#define T_    4096
#define DIN   512
#define RR    4096
#define DOUT  512
#define NINT  (RR + DIN)   // 4608
#define LEAK_ 0.9f

#define ROWS_MAX   28           // ceil(4096/148)
#define C_SH       2048         // half-cols of each row resident in SMEM
#define C_SH4      (C_SH / 4)   // 512 float4 s-chunks / uint2 w-chunks per row
#define RT8        8            // (RR-C_SH)/8/32 = reg-tail uint4 per row per lane
#define SMEM_BYTES ((size_t)ROWS_MAX * C_SH * 2 + RR * 4)  // 114688+16384=131072

#define TPB        256          // block size (reg cap 256/thread)

// ---------------------------------------------------------------------------
// Scratch (static __device__ arrays; runtime allocation is forbidden)
// ---------------------------------------------------------------------------
__device__ float  g_u[(size_t)T_ * RR];        // 64 MB
__device__ float  g_states[(size_t)T_ * RR];   // 64 MB
__device__ __half g_wres_h[(size_t)RR * RR];   // 32 MB: fp16 copy of Wres

// Monotonic step barrier (R13-proven)
__device__ unsigned g_count = 0;
__device__ unsigned g_gen = 0;

__device__ __forceinline__ float ldcg(const float* p) { return __ldcg(p); }
__device__ __forceinline__ float4 ldcg4f(const float4* p) {
    float4 v;
    asm volatile("ld.global.cg.v4.f32 {%0,%1,%2,%3}, [%4];"
                 : "=f"(v.x), "=f"(v.y), "=f"(v.z), "=f"(v.w) : "l"(p));
    return v;
}
__device__ __forceinline__ uint4 ldcg4u(const uint4* p) {
    uint4 v;
    asm volatile("ld.global.cg.v4.u32 {%0,%1,%2,%3}, [%4];"
                 : "=r"(v.x), "=r"(v.y), "=r"(v.z), "=r"(v.w) : "l"(p));
    return v;
}
__device__ __forceinline__ uint2 ldcg2u(const uint2* p) {
    uint2 v;
    asm volatile("ld.global.cg.v2.u32 {%0,%1}, [%2];"
                 : "=r"(v.x), "=r"(v.y) : "l"(p));
    return v;
}

// 4 halves (uint2) * float4 -> acc
__device__ __forceinline__ void fma4(uint2 w, float4 s, float& acc)
{
    float2 f0 = __half22float2(*reinterpret_cast<const __half2*>(&w.x));
    float2 f1 = __half22float2(*reinterpret_cast<const __half2*>(&w.y));
    acc = fmaf(f0.x, s.x, acc); acc = fmaf(f0.y, s.y, acc);
    acc = fmaf(f1.x, s.z, acc); acc = fmaf(f1.y, s.w, acc);
}
// 8 halves (uint4) * (float4,float4) -> acc
__device__ __forceinline__ void fma8(uint4 w, float4 s0, float4 s1, float& acc)
{
    float2 f;
    f = __half22float2(*reinterpret_cast<const __half2*>(&w.x));
    acc = fmaf(f.x, s0.x, acc); acc = fmaf(f.y, s0.y, acc);
    f = __half22float2(*reinterpret_cast<const __half2*>(&w.y));
    acc = fmaf(f.x, s0.z, acc); acc = fmaf(f.y, s0.w, acc);
    f = __half22float2(*reinterpret_cast<const __half2*>(&w.z));
    acc = fmaf(f.x, s1.x, acc); acc = fmaf(f.y, s1.y, acc);
    f = __half22float2(*reinterpret_cast<const __half2*>(&w.w));
    acc = fmaf(f.x, s1.z, acc); acc = fmaf(f.y, s1.w, acc);
}

// ---------------------------------------------------------------------------
// Monotonic scoped-atomic grid barrier (R13).
// ---------------------------------------------------------------------------
__device__ __forceinline__ void grid_barrier_step(int nctas, unsigned step)
{
    __syncthreads();
    if (threadIdx.x == 0) {
        unsigned old;
        asm volatile("atom.add.release.gpu.u32 %0, [%1], 1;"
                     : "=r"(old) : "l"(&g_count) : "memory");
        if (old + 1u == step * (unsigned)nctas) {
            asm volatile("st.release.gpu.u32 [%0], %1;"
                         :: "l"(&g_gen), "r"(step) : "memory");
        }
        unsigned cur;
        while (true) {
            asm volatile("ld.acquire.gpu.u32 %0, [%1];"
                         : "=r"(cur) : "l"(&g_gen) : "memory");
            if (cur >= step) break;
            __nanosleep(32);
        }
    }
    __syncthreads();
}

__global__ void reset_barrier_kernel()
{
    if (threadIdx.x == 0) { g_count = 0; g_gen = 0; }
}

// ---------------------------------------------------------------------------
// Convert Wres fp32 -> fp16 (once per launch)
// ---------------------------------------------------------------------------
__global__ __launch_bounds__(256) void convert_wres_kernel(const float* __restrict__ W)
{
    const size_t n8 = (size_t)RR * RR / 8;
    uint4* out = reinterpret_cast<uint4*>(g_wres_h);
    const float4* in = reinterpret_cast<const float4*>(W);
    for (size_t k = (size_t)blockIdx.x * blockDim.x + threadIdx.x;
         k < n8; k += (size_t)gridDim.x * blockDim.x) {
        float4 a = ldcg4f(in + 2 * k);
        float4 b = ldcg4f(in + 2 * k + 1);
        uint4 o;
        __half2 h;
        h = __floats2half2_rn(a.x, a.y); o.x = *reinterpret_cast<uint32_t*>(&h);
        h = __floats2half2_rn(a.z, a.w); o.y = *reinterpret_cast<uint32_t*>(&h);
        h = __floats2half2_rn(b.x, b.y); o.z = *reinterpret_cast<uint32_t*>(&h);
        h = __floats2half2_rn(b.z, b.w); o.w = *reinterpret_cast<uint32_t*>(&h);
        out[k] = o;
    }
}

// ---------------------------------------------------------------------------
// GEMM 1: g_u[t][r] = sum_d x[t,d] * Win_w[r,d] + Win_b[r]
// ---------------------------------------------------------------------------
__global__ __launch_bounds__(256) void gemm_u_kernel(
    const float* __restrict__ A, const float* __restrict__ B,
    const float* __restrict__ bias)
{
    const int K = DIN;
    __shared__ float As[8][128];
    __shared__ float Bs[8][128];

    const int bm = blockIdx.y * 128;
    const int bn = blockIdx.x * 128;
    const int tid = threadIdx.x;
    const int tm = (tid >> 4) * 8;
    const int tn = (tid & 15) * 8;
    const int lr = tid >> 1;
    const int lc = (tid & 1) * 4;

    float acc[8][8];
    #pragma unroll
    for (int i = 0; i < 8; i++)
        #pragma unroll
        for (int j = 0; j < 8; j++) acc[i][j] = 0.f;

    for (int kb = 0; kb < K; kb += 8) {
        float4 a = *reinterpret_cast<const float4*>(&A[(size_t)(bm + lr) * K + kb + lc]);
        float4 b = *reinterpret_cast<const float4*>(&B[(size_t)(bn + lr) * K + kb + lc]);
        __syncthreads();
        As[lc + 0][lr] = a.x; As[lc + 1][lr] = a.y; As[lc + 2][lr] = a.z; As[lc + 3][lr] = a.w;
        Bs[lc + 0][lr] = b.x; Bs[lc + 1][lr] = b.y; Bs[lc + 2][lr] = b.z; Bs[lc + 3][lr] = b.w;
        __syncthreads();
        #pragma unroll
        for (int k = 0; k < 8; k++) {
            float4 a0 = *reinterpret_cast<const float4*>(&As[k][tm]);
            float4 a1 = *reinterpret_cast<const float4*>(&As[k][tm + 4]);
            float4 b0 = *reinterpret_cast<const float4*>(&Bs[k][tn]);
            float4 b1 = *reinterpret_cast<const float4*>(&Bs[k][tn + 4]);
            float ar[8] = {a0.x, a0.y, a0.z, a0.w, a1.x, a1.y, a1.z, a1.w};
            float br[8] = {b0.x, b0.y, b0.z, b0.w, b1.x, b1.y, b1.z, b1.w};
            #pragma unroll
            for (int i = 0; i < 8; i++)
                #pragma unroll
                for (int j = 0; j < 8; j++)
                    acc[i][j] = fmaf(ar[i], br[j], acc[i][j]);
        }
    }

    #pragma unroll
    for (int i = 0; i < 8; i++)
        #pragma unroll
        for (int j = 0; j < 8; j++)
            g_u[(size_t)(bm + tm + i) * RR + (bn + tn + j)] = acc[i][j] + bias[bn + tn + j];
}

// ---------------------------------------------------------------------------
// Persistent recurrence, fp16 weights, TPB=256.
// 7 compute warps x 4 rows. Cols [0,C_SH)=2048 in SMEM; cols [C_SH,RR)=2048
// REGISTER-RESIDENT (4 rows x 8 uint4 per thread = 128 regs, loaded once).
// s fp32 staged to SMEM per step (4 float4/thread).
// ---------------------------------------------------------------------------
extern __shared__ unsigned char s_dyn[];

__global__ __launch_bounds__(TPB, 1) void recur_smem_kernel(int nctas)
{
    __half* wsh  = reinterpret_cast<__half*>(s_dyn);
    float*  s_sh = reinterpret_cast<float*>(s_dyn + (size_t)ROWS_MAX * C_SH * 2);
    float4* s_sh4 = reinterpret_cast<float4*>(s_sh);

    const int cta   = blockIdx.x;
    const int r0    = (cta * RR) / nctas;
    const int r1    = ((cta + 1) * RR) / nctas;
    const int nrows = r1 - r0;
    const int warp  = threadIdx.x >> 5;
    const int lane  = threadIdx.x & 31;
    const int tid   = threadIdx.x;

    // Prologue: copy resident weight block (cols [0,C_SH)) into SMEM
    {
        const int tot = nrows * (C_SH / 8);
        uint4* wsh4 = reinterpret_cast<uint4*>(wsh);
        for (int idx = tid; idx < tot; idx += TPB) {
            int lrow = idx / (C_SH / 8);
            int c8   = idx - lrow * (C_SH / 8);
            wsh4[(size_t)lrow * (C_SH / 8) + c8] =
                ldcg4u(reinterpret_cast<const uint4*>(g_wres_h + (size_t)(r0 + lrow) * RR) + c8);
        }
    }

    const int rowA   = r0 + 4 * warp;
    const bool active = (rowA < r1);
    bool rv[4];
    #pragma unroll
    for (int r = 0; r < 4; r++) rv[r] = active && (rowA + r < r1);

    // Register-resident tail weights (cols C_SH..RR-1), loaded ONCE.
    // Per thread: 4 rows x RT8 uint4 = 128 regs.
    uint4 tw[4][RT8];
    #pragma unroll
    for (int r = 0; r < 4; r++)
        #pragma unroll
        for (int k = 0; k < RT8; k++) {
            if (rv[r]) {
                const uint4* wg = reinterpret_cast<const uint4*>(
                    g_wres_h + (size_t)(rowA + r) * RR + C_SH);
                tw[r][k] = ldcg4u(wg + lane + 32 * k);
            } else {
                tw[r][k] = make_uint4(0, 0, 0, 0);
            }
        }

    const uint2* ws[4];
    #pragma unroll
    for (int r = 0; r < 4; r++)
        ws[r] = reinterpret_cast<const uint2*>(wsh + (size_t)(4 * warp + r) * C_SH);

    // step 0: states[0] = tanh(u[0])
    if (tid < nrows) {
        int r = r0 + tid;
        g_states[r] = tanhf(ldcg(&g_u[r]));
    }
    unsigned bstep = 1;
    grid_barrier_step(nctas, bstep++);

    for (int t = 1; t < T_; ++t) {
        // Prefetch u[t] (independent of the barrier)
        float uval = 0.f;
        if (active && lane < 4 && rv[lane])
            uval = ldcg(&g_u[(size_t)t * RR + rowA + lane]);

        // Stage s_{t-1} into SMEM (published by the previous barrier)
        {
            const float4* sp4 = reinterpret_cast<const float4*>(
                g_states + (size_t)(t - 1) * RR);
            #pragma unroll
            for (int k = 0; k < 4; k++)
                s_sh4[tid + k * TPB] = ldcg4f(sp4 + tid + k * TPB);
        }
        __syncthreads();

        if (active) {
            float acc0 = 0.f, acc1 = 0.f, acc2 = 0.f, acc3 = 0.f;

            // SMEM-resident columns [0, C_SH): dense layout
            #pragma unroll 4
            for (int idx = lane; idx < C_SH4; idx += 32) {
                float4 s = s_sh4[idx];
                fma4(ws[0][idx], s, acc0);
                fma4(ws[1][idx], s, acc1);
                fma4(ws[2][idx], s, acc2);
                fma4(ws[3][idx], s, acc3);
            }
            // Register-resident tail [C_SH, RR)
            #pragma unroll
            for (int k = 0; k < RT8; k++) {
                int idx = lane + 32 * k;
                float4 s0 = s_sh4[C_SH / 4 + 2 * idx];
                float4 s1 = s_sh4[C_SH / 4 + 2 * idx + 1];
                fma8(tw[0][k], s0, s1, acc0);
                fma8(tw[1][k], s0, s1, acc1);
                fma8(tw[2][k], s0, s1, acc2);
                fma8(tw[3][k], s0, s1, acc3);
            }

            #pragma unroll
            for (int o = 16; o; o >>= 1) {
                acc0 += __shfl_xor_sync(0xffffffffu, acc0, o);
                acc1 += __shfl_xor_sync(0xffffffffu, acc1, o);
                acc2 += __shfl_xor_sync(0xffffffffu, acc2, o);
                acc3 += __shfl_xor_sync(0xffffffffu, acc3, o);
            }
            if (lane < 4 && rv[lane]) {
                float sum = (lane == 0) ? acc0 :
                            (lane == 1) ? acc1 :
                            (lane == 2) ? acc2 : acc3;
                int row = rowA + lane;
                float xi = tanhf(uval + sum);
                g_states[(size_t)t * RR + row] =
                    (1.0f - LEAK_) * s_sh[row] + LEAK_ * xi;
            }
        }
        grid_barrier_step(nctas, bstep++);
    }
}

// ---------------------------------------------------------------------------
// Streaming fallback (no dynamic SMEM). Always resident. (block 1024)
// ---------------------------------------------------------------------------
__global__ __launch_bounds__(1024, 1) void recur_fallback(int nctas)
{
    __shared__ float fs[RR];
    float4* fs4 = reinterpret_cast<float4*>(fs);

    const int cta   = blockIdx.x;
    const int r0    = (cta * RR) / nctas;
    const int r1    = ((cta + 1) * RR) / nctas;
    const int nrows = r1 - r0;
    const int warp  = threadIdx.x >> 5;
    const int lane  = threadIdx.x & 31;
    const int tid   = threadIdx.x;

    if (tid < nrows) {
        int r = r0 + tid;
        g_states[r] = tanhf(ldcg(&g_u[r]));
    }
    unsigned bstep = 1;
    grid_barrier_step(nctas, bstep++);

    const int npairs = (nrows + 1) >> 1;
    const int rowA = r0 + 2 * warp;
    const int rowB = rowA + 1;
    const bool active = (warp < npairs);
    const bool haveB  = active && (rowB < r1);

    const uint2* wgA = reinterpret_cast<const uint2*>(g_wres_h + (size_t)rowA * RR);
    const uint2* wgB = reinterpret_cast<const uint2*>(g_wres_h + (size_t)rowB * RR);

    for (int t = 1; t < T_; ++t) {
        float uA = 0.f, uB = 0.f;
        if (active && lane == 0) {
            uA = ldcg(&g_u[(size_t)t * RR + rowA]);
            if (haveB) uB = ldcg(&g_u[(size_t)t * RR + rowB]);
        }
        {
            const float4* sp4 = reinterpret_cast<const float4*>(
                g_states + (size_t)(t - 1) * RR);
            fs4[tid] = ldcg4f(sp4 + tid);
        }
        __syncthreads();

        if (active) {
            float accA = 0.f, accB = 0.f;
            #pragma unroll 8
            for (int idx = lane; idx < RR / 4; idx += 32) {
                float4 s = fs4[idx];
                fma4(ldcg2u(wgA + idx), s, accA);
                if (haveB) fma4(ldcg2u(wgB + idx), s, accB);
            }
            #pragma unroll
            for (int o = 16; o; o >>= 1) {
                accA += __shfl_xor_sync(0xffffffffu, accA, o);
                accB += __shfl_xor_sync(0xffffffffu, accB, o);
            }
            if (lane == 0) {
                float* scur = g_states + (size_t)t * RR;
                float xiA = tanhf(uA + accA);
                scur[rowA] = (1.0f - LEAK_) * fs[rowA] + LEAK_ * xiA;
                if (haveB) {
                    float xiB = tanhf(uB + accB);
                    scur[rowB] = (1.0f - LEAK_) * fs[rowB] + LEAK_ * xiB;
                }
            }
        }
        grid_barrier_step(nctas, bstep++);
    }
}

// ---------------------------------------------------------------------------
// GEMM 2: yout = concat(x, states) @ Wout^T + b
// ---------------------------------------------------------------------------
__global__ __launch_bounds__(256) void gemm_out_kernel(
    const float* __restrict__ x, const float* __restrict__ Wout,
    const float* __restrict__ bias, float* __restrict__ C)
{
    const int K = NINT;
    __shared__ float As[8][128];
    __shared__ float Bs[8][128];

    const int bm = blockIdx.y * 128;
    const int bn = blockIdx.x * 128;
    const int tid = threadIdx.x;
    const int tm = (tid >> 4) * 8;
    const int tn = (tid & 15) * 8;
    const int lr = tid >> 1;
    const int lc = (tid & 1) * 4;

    float acc[8][8];
    #pragma unroll
    for (int i = 0; i < 8; i++)
        #pragma unroll
        for (int j = 0; j < 8; j++) acc[i][j] = 0.f;

    for (int kb = 0; kb < K; kb += 8) {
        const int row = bm + lr;
        const int kk  = kb + lc;
        float4 a;
        if (kk < DIN)
            a = *reinterpret_cast<const float4*>(&x[(size_t)row * DIN + kk]);
        else
            a = *reinterpret_cast<const float4*>(&g_states[(size_t)row * RR + (kk - DIN)]);
        float4 b = *reinterpret_cast<const float4*>(&Wout[(size_t)(bn + lr) * K + kk]);
        __syncthreads();
        As[lc + 0][lr] = a.x; As[lc + 1][lr] = a.y; As[lc + 2][lr] = a.z; As[lc + 3][lr] = a.w;
        Bs[lc + 0][lr] = b.x; Bs[lc + 1][lr] = b.y; Bs[lc + 2][lr] = b.z; Bs[lc + 3][lr] = b.w;
        __syncthreads();
        #pragma unroll
        for (int k = 0; k < 8; k++) {
            float4 a0 = *reinterpret_cast<const float4*>(&As[k][tm]);
            float4 a1 = *reinterpret_cast<const float4*>(&As[k][tm + 4]);
            float4 b0 = *reinterpret_cast<const float4*>(&Bs[k][tn]);
            float4 b1 = *reinterpret_cast<const float4*>(&Bs[k][tn + 4]);
            float ar[8] = {a0.x, a0.y, a0.z, a0.w, a1.x, a1.y, a1.z, a1.w};
            float br[8] = {b0.x, b0.y, b0.z, b0.w, b1.x, b1.y, b1.z, b1.w};
            #pragma unroll
            for (int i = 0; i < 8; i++)
                #pragma unroll
                for (int j = 0; j < 8; j++)
                    acc[i][j] = fmaf(ar[i], br[j], acc[i][j]);
        }
    }

    #pragma unroll
    for (int i = 0; i < 8; i++)
        #pragma unroll
        for (int j = 0; j < 8; j++)
            C[(size_t)(bm + tm + i) * DOUT + (bn + tn + j)] = acc[i][j] + bias[bn + tn + j];
}

// ---------------------------------------------------------------------------
extern "C" void kernel_launch(void* const* d_in, const int* in_sizes, int n_in,
                              void* d_out, int out_size)
{
    const float* x      = (const float*)d_in[0];
    const float* Win_w  = (const float*)d_in[1];
    const float* Win_b  = (const float*)d_in[2];
    const float* Wres_w = (const float*)d_in[3];
    const float* Wout_w = (const float*)d_in[4];
    const float* Wout_b = (const float*)d_in[5];
    float* yout = (float*)d_out;

    int dev = 0;
    cudaGetDevice(&dev);
    int sms = 148;
    cudaDeviceGetAttribute(&sms, cudaDevAttrMultiProcessorCount, dev);
    if (sms < 64) sms = 64;
    if (sms > 256) sms = 256;

    cudaError_t attr_err = cudaFuncSetAttribute(
        recur_smem_kernel, cudaFuncAttributeMaxDynamicSharedMemorySize, (int)SMEM_BYTES);
    int nblk = 0;
    cudaError_t occ_err = cudaOccupancyMaxActiveBlocksPerMultiprocessor(
        &nblk, recur_smem_kernel, TPB, SMEM_BYTES);
    const int max_rows = (RR + sms - 1) / sms;
    const bool use_smem = (attr_err == cudaSuccess) &&
                          (occ_err == cudaSuccess) && (nblk >= 1) &&
                          (max_rows <= ROWS_MAX);

    reset_barrier_kernel<<<1, 32>>>();
    convert_wres_kernel<<<1024, 256>>>(Wres_w);

    dim3 g1(RR / 128, T_ / 128);
    gemm_u_kernel<<<g1, 256>>>(x, Win_w, Win_b);

    if (use_smem)
        recur_smem_kernel<<<sms, TPB, SMEM_BYTES>>>(sms);
    else
        recur_fallback<<<sms, 1024>>>(sms);

    dim3 g2(DOUT / 128, T_ / 128);
    gemm_out_kernel<<<g2, 256>>>(x, Wout_w, Wout_b, yout);

    (void)in_sizes; (void)n_in; (void)out_size;
}

// round 15
// speedup vs baseline: 1.1395x; 1.1395x over previous
#include <cuda_runtime.h>
#include <cuda_fp16.h>
#include <cstddef>
#include <cstdint>

// Problem constants (fixed shapes from reference)
#define T_    4096
#define DIN   512
#define RR    4096
#define DOUT  512
#define NINT  (RR + DIN)   // 4608
#define LEAK_ 0.9f

#define ROWS_MAX   28           // ceil(4096/148)
#define C_SH       3584         // half-cols of each row resident in SMEM
#define C_SH4      (C_SH / 4)   // 896 4-col chunks per row
#define RT8        2            // (RR-C_SH)/8/32 reg-tail uint4 per row per lane
#define SMEM_BYTES ((size_t)ROWS_MAX * C_SH * 2 + RR * 2)  // 200704+8192=208896

#define TPB        512          // block size for the recurrence

// ---------------------------------------------------------------------------
// Scratch (static __device__ arrays; runtime allocation is forbidden)
// ---------------------------------------------------------------------------
__device__ float  g_u[(size_t)T_ * RR];        // 64 MB
__device__ float  g_states[(size_t)T_ * RR];   // 64 MB (fp32; SMEM copy is fp16)
__device__ __half g_wres_h[(size_t)RR * RR];   // 32 MB: fp16 copy of Wres

// Monotonic step barrier (R13-proven)
__device__ unsigned g_count = 0;
__device__ unsigned g_gen = 0;

__device__ __forceinline__ float ldcg(const float* p) { return __ldcg(p); }
__device__ __forceinline__ float4 ldcg4f(const float4* p) {
    float4 v;
    asm volatile("ld.global.cg.v4.f32 {%0,%1,%2,%3}, [%4];"
                 : "=f"(v.x), "=f"(v.y), "=f"(v.z), "=f"(v.w) : "l"(p));
    return v;
}
__device__ __forceinline__ uint4 ldcg4u(const uint4* p) {
    uint4 v;
    asm volatile("ld.global.cg.v4.u32 {%0,%1,%2,%3}, [%4];"
                 : "=r"(v.x), "=r"(v.y), "=r"(v.z), "=r"(v.w) : "l"(p));
    return v;
}
__device__ __forceinline__ uint2 ldcg2u(const uint2* p) {
    uint2 v;
    asm volatile("ld.global.cg.v2.u32 {%0,%1}, [%2];"
                 : "=r"(v.x), "=r"(v.y) : "l"(p));
    return v;
}

__device__ __forceinline__ float2 h2f(uint32_t h)
{
    return __half22float2(*reinterpret_cast<const __half2*>(&h));
}

// 4 halves (uint2) * float4 -> acc
__device__ __forceinline__ void fma4(uint2 w, float4 s, float& acc)
{
    float2 f0 = h2f(w.x);
    float2 f1 = h2f(w.y);
    acc = fmaf(f0.x, s.x, acc); acc = fmaf(f0.y, s.y, acc);
    acc = fmaf(f1.x, s.z, acc); acc = fmaf(f1.y, s.w, acc);
}
// 8 halves (uint4) * (float4,float4) -> acc
__device__ __forceinline__ void fma8(uint4 w, float4 s0, float4 s1, float& acc)
{
    float2 f;
    f = h2f(w.x); acc = fmaf(f.x, s0.x, acc); acc = fmaf(f.y, s0.y, acc);
    f = h2f(w.y); acc = fmaf(f.x, s0.z, acc); acc = fmaf(f.y, s0.w, acc);
    f = h2f(w.z); acc = fmaf(f.x, s1.x, acc); acc = fmaf(f.y, s1.y, acc);
    f = h2f(w.w); acc = fmaf(f.x, s1.z, acc); acc = fmaf(f.y, s1.w, acc);
}

// ---------------------------------------------------------------------------
// Monotonic scoped-atomic grid barrier (R13).
// ---------------------------------------------------------------------------
__device__ __forceinline__ void grid_barrier_step(int nctas, unsigned step)
{
    __syncthreads();
    if (threadIdx.x == 0) {
        unsigned old;
        asm volatile("atom.add.release.gpu.u32 %0, [%1], 1;"
                     : "=r"(old) : "l"(&g_count) : "memory");
        if (old + 1u == step * (unsigned)nctas) {
            asm volatile("st.release.gpu.u32 [%0], %1;"
                         :: "l"(&g_gen), "r"(step) : "memory");
        }
        unsigned cur;
        while (true) {
            asm volatile("ld.acquire.gpu.u32 %0, [%1];"
                         : "=r"(cur) : "l"(&g_gen) : "memory");
            if (cur >= step) break;
            __nanosleep(32);
        }
    }
    __syncthreads();
}

__global__ void reset_barrier_kernel()
{
    if (threadIdx.x == 0) { g_count = 0; g_gen = 0; }
}

// ---------------------------------------------------------------------------
// Convert Wres fp32 -> fp16 (once per launch)
// ---------------------------------------------------------------------------
__global__ __launch_bounds__(256) void convert_wres_kernel(const float* __restrict__ W)
{
    const size_t n8 = (size_t)RR * RR / 8;
    uint4* out = reinterpret_cast<uint4*>(g_wres_h);
    const float4* in = reinterpret_cast<const float4*>(W);
    for (size_t k = (size_t)blockIdx.x * blockDim.x + threadIdx.x;
         k < n8; k += (size_t)gridDim.x * blockDim.x) {
        float4 a = ldcg4f(in + 2 * k);
        float4 b = ldcg4f(in + 2 * k + 1);
        uint4 o;
        __half2 h;
        h = __floats2half2_rn(a.x, a.y); o.x = *reinterpret_cast<uint32_t*>(&h);
        h = __floats2half2_rn(a.z, a.w); o.y = *reinterpret_cast<uint32_t*>(&h);
        h = __floats2half2_rn(b.x, b.y); o.z = *reinterpret_cast<uint32_t*>(&h);
        h = __floats2half2_rn(b.z, b.w); o.w = *reinterpret_cast<uint32_t*>(&h);
        out[k] = o;
    }
}

// ---------------------------------------------------------------------------
// GEMM 1: g_u[t][r] = sum_d x[t,d] * Win_w[r,d] + Win_b[r]
// ---------------------------------------------------------------------------
__global__ __launch_bounds__(256) void gemm_u_kernel(
    const float* __restrict__ A, const float* __restrict__ B,
    const float* __restrict__ bias)
{
    const int K = DIN;
    __shared__ float As[8][128];
    __shared__ float Bs[8][128];

    const int bm = blockIdx.y * 128;
    const int bn = blockIdx.x * 128;
    const int tid = threadIdx.x;
    const int tm = (tid >> 4) * 8;
    const int tn = (tid & 15) * 8;
    const int lr = tid >> 1;
    const int lc = (tid & 1) * 4;

    float acc[8][8];
    #pragma unroll
    for (int i = 0; i < 8; i++)
        #pragma unroll
        for (int j = 0; j < 8; j++) acc[i][j] = 0.f;

    for (int kb = 0; kb < K; kb += 8) {
        float4 a = *reinterpret_cast<const float4*>(&A[(size_t)(bm + lr) * K + kb + lc]);
        float4 b = *reinterpret_cast<const float4*>(&B[(size_t)(bn + lr) * K + kb + lc]);
        __syncthreads();
        As[lc + 0][lr] = a.x; As[lc + 1][lr] = a.y; As[lc + 2][lr] = a.z; As[lc + 3][lr] = a.w;
        Bs[lc + 0][lr] = b.x; Bs[lc + 1][lr] = b.y; Bs[lc + 2][lr] = b.z; Bs[lc + 3][lr] = b.w;
        __syncthreads();
        #pragma unroll
        for (int k = 0; k < 8; k++) {
            float4 a0 = *reinterpret_cast<const float4*>(&As[k][tm]);
            float4 a1 = *reinterpret_cast<const float4*>(&As[k][tm + 4]);
            float4 b0 = *reinterpret_cast<const float4*>(&Bs[k][tn]);
            float4 b1 = *reinterpret_cast<const float4*>(&Bs[k][tn + 4]);
            float ar[8] = {a0.x, a0.y, a0.z, a0.w, a1.x, a1.y, a1.z, a1.w};
            float br[8] = {b0.x, b0.y, b0.z, b0.w, b1.x, b1.y, b1.z, b1.w};
            #pragma unroll
            for (int i = 0; i < 8; i++)
                #pragma unroll
                for (int j = 0; j < 8; j++)
                    acc[i][j] = fmaf(ar[i], br[j], acc[i][j]);
        }
    }

    #pragma unroll
    for (int i = 0; i < 8; i++)
        #pragma unroll
        for (int j = 0; j < 8; j++)
            g_u[(size_t)(bm + tm + i) * RR + (bn + tn + j)] = acc[i][j] + bias[bn + tn + j];
}

// ---------------------------------------------------------------------------
// Persistent recurrence (R13 structure), fp16 weights + fp16 staged s.
// Block 512. 7 compute warps x 4 rows. Cols [0,C_SH) in SMEM (half),
// cols [C_SH,RR) register-resident. s staged to SMEM as HALF per step.
// ---------------------------------------------------------------------------
extern __shared__ unsigned char s_dyn[];

__global__ __launch_bounds__(TPB, 1) void recur_smem_kernel(int nctas)
{
    __half* wsh  = reinterpret_cast<__half*>(s_dyn);
    __half* s_shh = reinterpret_cast<__half*>(s_dyn + (size_t)ROWS_MAX * C_SH * 2);
    uint2*  s_sh2 = reinterpret_cast<uint2*>(s_shh);   // 4 halves per entry
    uint4*  s_sh4h = reinterpret_cast<uint4*>(s_shh);  // 8 halves per entry

    const int cta   = blockIdx.x;
    const int r0    = (cta * RR) / nctas;
    const int r1    = ((cta + 1) * RR) / nctas;
    const int nrows = r1 - r0;
    const int warp  = threadIdx.x >> 5;
    const int lane  = threadIdx.x & 31;
    const int tid   = threadIdx.x;

    // Prologue: copy resident weight block (cols [0,C_SH)) into SMEM
    {
        const int tot = nrows * (C_SH / 8);
        uint4* wsh4 = reinterpret_cast<uint4*>(wsh);
        for (int idx = tid; idx < tot; idx += TPB) {
            int lrow = idx / (C_SH / 8);
            int c8   = idx - lrow * (C_SH / 8);
            wsh4[(size_t)lrow * (C_SH / 8) + c8] =
                ldcg4u(reinterpret_cast<const uint4*>(g_wres_h + (size_t)(r0 + lrow) * RR) + c8);
        }
    }

    const int rowA   = r0 + 4 * warp;
    const bool active = (rowA < r1);
    bool rv[4];
    #pragma unroll
    for (int r = 0; r < 4; r++) rv[r] = active && (rowA + r < r1);

    // Register-resident tail weights (cols C_SH..RR-1), loaded ONCE.
    uint4 tw[4][RT8];
    #pragma unroll
    for (int r = 0; r < 4; r++)
        #pragma unroll
        for (int k = 0; k < RT8; k++) {
            if (rv[r]) {
                const uint4* wg = reinterpret_cast<const uint4*>(
                    g_wres_h + (size_t)(rowA + r) * RR + C_SH);
                tw[r][k] = ldcg4u(wg + lane + 32 * k);
            } else {
                tw[r][k] = make_uint4(0, 0, 0, 0);
            }
        }

    const uint2* ws[4];
    #pragma unroll
    for (int r = 0; r < 4; r++)
        ws[r] = reinterpret_cast<const uint2*>(wsh + (size_t)(4 * warp + r) * C_SH);

    // step 0: states[0] = tanh(u[0])
    if (tid < nrows) {
        int r = r0 + tid;
        g_states[r] = tanhf(ldcg(&g_u[r]));
    }
    unsigned bstep = 1;
    grid_barrier_step(nctas, bstep++);

    for (int t = 1; t < T_; ++t) {
        // Prefetch u[t] (independent of the barrier)
        float uval = 0.f;
        if (active && lane < 4 && rv[lane])
            uval = ldcg(&g_u[(size_t)t * RR + rowA + lane]);

        // Stage s_{t-1} into SMEM as HALF (each thread: 8 floats -> 8 halves)
        {
            const float4* sp4 = reinterpret_cast<const float4*>(
                g_states + (size_t)(t - 1) * RR);
            float4 a = ldcg4f(sp4 + 2 * tid);
            float4 b = ldcg4f(sp4 + 2 * tid + 1);
            uint4 o;
            __half2 h;
            h = __floats2half2_rn(a.x, a.y); o.x = *reinterpret_cast<uint32_t*>(&h);
            h = __floats2half2_rn(a.z, a.w); o.y = *reinterpret_cast<uint32_t*>(&h);
            h = __floats2half2_rn(b.x, b.y); o.z = *reinterpret_cast<uint32_t*>(&h);
            h = __floats2half2_rn(b.z, b.w); o.w = *reinterpret_cast<uint32_t*>(&h);
            s_sh4h[tid] = o;
        }
        __syncthreads();

        if (active) {
            float acc0 = 0.f, acc1 = 0.f, acc2 = 0.f, acc3 = 0.f;

            // SMEM-resident columns [0, C_SH): s read as 4 halves (8B/lane)
            #pragma unroll 4
            for (int idx = lane; idx < C_SH4; idx += 32) {
                uint2 s2 = s_sh2[idx];
                float2 sa = h2f(s2.x);
                float2 sb = h2f(s2.y);
                float4 s = make_float4(sa.x, sa.y, sb.x, sb.y);
                fma4(ws[0][idx], s, acc0);
                fma4(ws[1][idx], s, acc1);
                fma4(ws[2][idx], s, acc2);
                fma4(ws[3][idx], s, acc3);
            }
            // Register-resident tail [C_SH, RR): s read as 8 halves
            #pragma unroll
            for (int k = 0; k < RT8; k++) {
                int idx = lane + 32 * k;
                uint4 s8 = s_sh4h[C_SH / 8 + idx];
                float2 f0 = h2f(s8.x), f1 = h2f(s8.y);
                float2 f2 = h2f(s8.z), f3 = h2f(s8.w);
                float4 s0 = make_float4(f0.x, f0.y, f1.x, f1.y);
                float4 s1 = make_float4(f2.x, f2.y, f3.x, f3.y);
                fma8(tw[0][k], s0, s1, acc0);
                fma8(tw[1][k], s0, s1, acc1);
                fma8(tw[2][k], s0, s1, acc2);
                fma8(tw[3][k], s0, s1, acc3);
            }

            #pragma unroll
            for (int o = 16; o; o >>= 1) {
                acc0 += __shfl_xor_sync(0xffffffffu, acc0, o);
                acc1 += __shfl_xor_sync(0xffffffffu, acc1, o);
                acc2 += __shfl_xor_sync(0xffffffffu, acc2, o);
                acc3 += __shfl_xor_sync(0xffffffffu, acc3, o);
            }
            if (lane < 4 && rv[lane]) {
                float sum = (lane == 0) ? acc0 :
                            (lane == 1) ? acc1 :
                            (lane == 2) ? acc2 : acc3;
                int row = rowA + lane;
                // leak uses the fp32 previous state from gmem (exact)
                float sprev = ldcg(&g_states[(size_t)(t - 1) * RR + row]);
                float xi = tanhf(uval + sum);
                g_states[(size_t)t * RR + row] =
                    (1.0f - LEAK_) * sprev + LEAK_ * xi;
            }
        }
        grid_barrier_step(nctas, bstep++);
    }
}

// ---------------------------------------------------------------------------
// Streaming fallback (no dynamic SMEM). Always resident. (block 1024)
// ---------------------------------------------------------------------------
__global__ __launch_bounds__(1024, 1) void recur_fallback(int nctas)
{
    __shared__ float fs[RR];
    float4* fs4 = reinterpret_cast<float4*>(fs);

    const int cta   = blockIdx.x;
    const int r0    = (cta * RR) / nctas;
    const int r1    = ((cta + 1) * RR) / nctas;
    const int nrows = r1 - r0;
    const int warp  = threadIdx.x >> 5;
    const int lane  = threadIdx.x & 31;
    const int tid   = threadIdx.x;

    if (tid < nrows) {
        int r = r0 + tid;
        g_states[r] = tanhf(ldcg(&g_u[r]));
    }
    unsigned bstep = 1;
    grid_barrier_step(nctas, bstep++);

    const int npairs = (nrows + 1) >> 1;
    const int rowA = r0 + 2 * warp;
    const int rowB = rowA + 1;
    const bool active = (warp < npairs);
    const bool haveB  = active && (rowB < r1);

    const uint2* wgA = reinterpret_cast<const uint2*>(g_wres_h + (size_t)rowA * RR);
    const uint2* wgB = reinterpret_cast<const uint2*>(g_wres_h + (size_t)rowB * RR);

    for (int t = 1; t < T_; ++t) {
        float uA = 0.f, uB = 0.f;
        if (active && lane == 0) {
            uA = ldcg(&g_u[(size_t)t * RR + rowA]);
            if (haveB) uB = ldcg(&g_u[(size_t)t * RR + rowB]);
        }
        {
            const float4* sp4 = reinterpret_cast<const float4*>(
                g_states + (size_t)(t - 1) * RR);
            fs4[tid] = ldcg4f(sp4 + tid);
        }
        __syncthreads();

        if (active) {
            float accA = 0.f, accB = 0.f;
            #pragma unroll 8
            for (int idx = lane; idx < RR / 4; idx += 32) {
                float4 s = fs4[idx];
                fma4(ldcg2u(wgA + idx), s, accA);
                if (haveB) fma4(ldcg2u(wgB + idx), s, accB);
            }
            #pragma unroll
            for (int o = 16; o; o >>= 1) {
                accA += __shfl_xor_sync(0xffffffffu, accA, o);
                accB += __shfl_xor_sync(0xffffffffu, accB, o);
            }
            if (lane == 0) {
                float* scur = g_states + (size_t)t * RR;
                float xiA = tanhf(uA + accA);
                scur[rowA] = (1.0f - LEAK_) * fs[rowA] + LEAK_ * xiA;
                if (haveB) {
                    float xiB = tanhf(uB + accB);
                    scur[rowB] = (1.0f - LEAK_) * fs[rowB] + LEAK_ * xiB;
                }
            }
        }
        grid_barrier_step(nctas, bstep++);
    }
}

// ---------------------------------------------------------------------------
// GEMM 2: yout = concat(x, states) @ Wout^T + b
// ---------------------------------------------------------------------------
__global__ __launch_bounds__(256) void gemm_out_kernel(
    const float* __restrict__ x, const float* __restrict__ Wout,
    const float* __restrict__ bias, float* __restrict__ C)
{
    const int K = NINT;
    __shared__ float As[8][128];
    __shared__ float Bs[8][128];

    const int bm = blockIdx.y * 128;
    const int bn = blockIdx.x * 128;
    const int tid = threadIdx.x;
    const int tm = (tid >> 4) * 8;
    const int tn = (tid & 15) * 8;
    const int lr = tid >> 1;
    const int lc = (tid & 1) * 4;

    float acc[8][8];
    #pragma unroll
    for (int i = 0; i < 8; i++)
        #pragma unroll
        for (int j = 0; j < 8; j++) acc[i][j] = 0.f;

    for (int kb = 0; kb < K; kb += 8) {
        const int row = bm + lr;
        const int kk  = kb + lc;
        float4 a;
        if (kk < DIN)
            a = *reinterpret_cast<const float4*>(&x[(size_t)row * DIN + kk]);
        else
            a = *reinterpret_cast<const float4*>(&g_states[(size_t)row * RR + (kk - DIN)]);
        float4 b = *reinterpret_cast<const float4*>(&Wout[(size_t)(bn + lr) * K + kk]);
        __syncthreads();
        As[lc + 0][lr] = a.x; As[lc + 1][lr] = a.y; As[lc + 2][lr] = a.z; As[lc + 3][lr] = a.w;
        Bs[lc + 0][lr] = b.x; Bs[lc + 1][lr] = b.y; Bs[lc + 2][lr] = b.z; Bs[lc + 3][lr] = b.w;
        __syncthreads();
        #pragma unroll
        for (int k = 0; k < 8; k++) {
            float4 a0 = *reinterpret_cast<const float4*>(&As[k][tm]);
            float4 a1 = *reinterpret_cast<const float4*>(&As[k][tm + 4]);
            float4 b0 = *reinterpret_cast<const float4*>(&Bs[k][tn]);
            float4 b1 = *reinterpret_cast<const float4*>(&Bs[k][tn + 4]);
            float ar[8] = {a0.x, a0.y, a0.z, a0.w, a1.x, a1.y, a1.z, a1.w};
            float br[8] = {b0.x, b0.y, b0.z, b0.w, b1.x, b1.y, b1.z, b1.w};
            #pragma unroll
            for (int i = 0; i < 8; i++)
                #pragma unroll
                for (int j = 0; j < 8; j++)
                    acc[i][j] = fmaf(ar[i], br[j], acc[i][j]);
        }
    }

    #pragma unroll
    for (int i = 0; i < 8; i++)
        #pragma unroll
        for (int j = 0; j < 8; j++)
            C[(size_t)(bm + tm + i) * DOUT + (bn + tn + j)] = acc[i][j] + bias[bn + tn + j];
}

// ---------------------------------------------------------------------------
extern "C" void kernel_launch(void* const* d_in, const int* in_sizes, int n_in,
                              void* d_out, int out_size)
{
    const float* x      = (const float*)d_in[0];
    const float* Win_w  = (const float*)d_in[1];
    const float* Win_b  = (const float*)d_in[2];
    const float* Wres_w = (const float*)d_in[3];
    const float* Wout_w = (const float*)d_in[4];
    const float* Wout_b = (const float*)d_in[5];
    float* yout = (float*)d_out;

    int dev = 0;
    cudaGetDevice(&dev);
    int sms = 148;
    cudaDeviceGetAttribute(&sms, cudaDevAttrMultiProcessorCount, dev);
    if (sms < 64) sms = 64;
    if (sms > 256) sms = 256;

    cudaError_t attr_err = cudaFuncSetAttribute(
        recur_smem_kernel, cudaFuncAttributeMaxDynamicSharedMemorySize, (int)SMEM_BYTES);
    int nblk = 0;
    cudaError_t occ_err = cudaOccupancyMaxActiveBlocksPerMultiprocessor(
        &nblk, recur_smem_kernel, TPB, SMEM_BYTES);
    const int max_rows = (RR + sms - 1) / sms;
    const bool use_smem = (attr_err == cudaSuccess) &&
                          (occ_err == cudaSuccess) && (nblk >= 1) &&
                          (max_rows <= ROWS_MAX);

    reset_barrier_kernel<<<1, 32>>>();
    convert_wres_kernel<<<1024, 256>>>(Wres_w);

    dim3 g1(RR / 128, T_ / 128);
    gemm_u_kernel<<<g1, 256>>>(x, Win_w, Win_b);

    if (use_smem)
        recur_smem_kernel<<<sms, TPB, SMEM_BYTES>>>(sms);
    else
        recur_fallback<<<sms, 1024>>>(sms);

    dim3 g2(DOUT / 128, T_ / 128);
    gemm_out_kernel<<<g2, 256>>>(x, Wout_w, Wout_b, yout);

    (void)in_sizes; (void)n_in; (void)out_size;
}

// round 16
// speedup vs baseline: 1.2697x; 1.1143x over previous
#include <cuda_runtime.h>
#include <cuda_fp16.h>
#include <cstddef>
#include <cstdint>

// Problem constants (fixed shapes from reference)
#define T_    4096
#define DIN   512
#define RR    4096
#define DOUT  512
#define NINT  (RR + DIN)   // 4608
#define LEAK_ 0.9f

#define ROWS_MAX   28           // ceil(4096/148)
#define C_SH       3584         // half-cols of each row resident in SMEM
#define C_SH8      (C_SH / 8)   // 448 8-col chunks per row
#define RT8        2            // (RR-C_SH)/8/32 reg-tail uint4 per row per lane
#define SMEM_BYTES ((size_t)ROWS_MAX * C_SH * 2 + RR * 2)  // 200704+8192=208896

#define TPB        512          // block size for the recurrence

// ---------------------------------------------------------------------------
// Scratch (static __device__ arrays; runtime allocation is forbidden)
// ---------------------------------------------------------------------------
__device__ float  g_u[(size_t)T_ * RR];        // 64 MB
__device__ float  g_states[(size_t)T_ * RR];   // 64 MB (fp32; SMEM copy is fp16)
__device__ __half g_wres_h[(size_t)RR * RR];   // 32 MB: fp16 copy of Wres

// Monotonic step barrier (R13-proven)
__device__ unsigned g_count = 0;
__device__ unsigned g_gen = 0;

__device__ __forceinline__ float ldcg(const float* p) { return __ldcg(p); }
__device__ __forceinline__ float4 ldcg4f(const float4* p) {
    float4 v;
    asm volatile("ld.global.cg.v4.f32 {%0,%1,%2,%3}, [%4];"
                 : "=f"(v.x), "=f"(v.y), "=f"(v.z), "=f"(v.w) : "l"(p));
    return v;
}
__device__ __forceinline__ uint4 ldcg4u(const uint4* p) {
    uint4 v;
    asm volatile("ld.global.cg.v4.u32 {%0,%1,%2,%3}, [%4];"
                 : "=r"(v.x), "=r"(v.y), "=r"(v.z), "=r"(v.w) : "l"(p));
    return v;
}
__device__ __forceinline__ uint2 ldcg2u(const uint2* p) {
    uint2 v;
    asm volatile("ld.global.cg.v2.u32 {%0,%1}, [%2];"
                 : "=r"(v.x), "=r"(v.y) : "l"(p));
    return v;
}

__device__ __forceinline__ float2 h2f(uint32_t h)
{
    return __half22float2(*reinterpret_cast<const __half2*>(&h));
}

// 8-col fp16 dot: half2 chain (4 HFMA2-class ops), flushed to fp32.
// 4-term partials per half2 slot keep fp16 accumulation error negligible.
__device__ __forceinline__ float dot8(uint4 w, uint4 s)
{
    const __half2* wh = reinterpret_cast<const __half2*>(&w);
    const __half2* sh = reinterpret_cast<const __half2*>(&s);
    __half2 acc = __hmul2(wh[0], sh[0]);
    acc = __hfma2(wh[1], sh[1], acc);
    acc = __hfma2(wh[2], sh[2], acc);
    acc = __hfma2(wh[3], sh[3], acc);
    float2 f = __half22float2(acc);
    return f.x + f.y;
}

// 4 halves (uint2) * float4 -> acc (fallback kernel)
__device__ __forceinline__ void fma4(uint2 w, float4 s, float& acc)
{
    float2 f0 = h2f(w.x);
    float2 f1 = h2f(w.y);
    acc = fmaf(f0.x, s.x, acc); acc = fmaf(f0.y, s.y, acc);
    acc = fmaf(f1.x, s.z, acc); acc = fmaf(f1.y, s.w, acc);
}

// ---------------------------------------------------------------------------
// Monotonic scoped-atomic grid barrier (R13).
// ---------------------------------------------------------------------------
__device__ __forceinline__ void grid_barrier_step(int nctas, unsigned step)
{
    __syncthreads();
    if (threadIdx.x == 0) {
        unsigned old;
        asm volatile("atom.add.release.gpu.u32 %0, [%1], 1;"
                     : "=r"(old) : "l"(&g_count) : "memory");
        if (old + 1u == step * (unsigned)nctas) {
            asm volatile("st.release.gpu.u32 [%0], %1;"
                         :: "l"(&g_gen), "r"(step) : "memory");
        }
        unsigned cur;
        while (true) {
            asm volatile("ld.acquire.gpu.u32 %0, [%1];"
                         : "=r"(cur) : "l"(&g_gen) : "memory");
            if (cur >= step) break;
            __nanosleep(32);
        }
    }
    __syncthreads();
}

__global__ void reset_barrier_kernel()
{
    if (threadIdx.x == 0) { g_count = 0; g_gen = 0; }
}

// ---------------------------------------------------------------------------
// Convert Wres fp32 -> fp16 (once per launch)
// ---------------------------------------------------------------------------
__global__ __launch_bounds__(256) void convert_wres_kernel(const float* __restrict__ W)
{
    const size_t n8 = (size_t)RR * RR / 8;
    uint4* out = reinterpret_cast<uint4*>(g_wres_h);
    const float4* in = reinterpret_cast<const float4*>(W);
    for (size_t k = (size_t)blockIdx.x * blockDim.x + threadIdx.x;
         k < n8; k += (size_t)gridDim.x * blockDim.x) {
        float4 a = ldcg4f(in + 2 * k);
        float4 b = ldcg4f(in + 2 * k + 1);
        uint4 o;
        __half2 h;
        h = __floats2half2_rn(a.x, a.y); o.x = *reinterpret_cast<uint32_t*>(&h);
        h = __floats2half2_rn(a.z, a.w); o.y = *reinterpret_cast<uint32_t*>(&h);
        h = __floats2half2_rn(b.x, b.y); o.z = *reinterpret_cast<uint32_t*>(&h);
        h = __floats2half2_rn(b.z, b.w); o.w = *reinterpret_cast<uint32_t*>(&h);
        out[k] = o;
    }
}

// ---------------------------------------------------------------------------
// GEMM 1: g_u[t][r] = sum_d x[t,d] * Win_w[r,d] + Win_b[r]
// ---------------------------------------------------------------------------
__global__ __launch_bounds__(256) void gemm_u_kernel(
    const float* __restrict__ A, const float* __restrict__ B,
    const float* __restrict__ bias)
{
    const int K = DIN;
    __shared__ float As[8][128];
    __shared__ float Bs[8][128];

    const int bm = blockIdx.y * 128;
    const int bn = blockIdx.x * 128;
    const int tid = threadIdx.x;
    const int tm = (tid >> 4) * 8;
    const int tn = (tid & 15) * 8;
    const int lr = tid >> 1;
    const int lc = (tid & 1) * 4;

    float acc[8][8];
    #pragma unroll
    for (int i = 0; i < 8; i++)
        #pragma unroll
        for (int j = 0; j < 8; j++) acc[i][j] = 0.f;

    for (int kb = 0; kb < K; kb += 8) {
        float4 a = *reinterpret_cast<const float4*>(&A[(size_t)(bm + lr) * K + kb + lc]);
        float4 b = *reinterpret_cast<const float4*>(&B[(size_t)(bn + lr) * K + kb + lc]);
        __syncthreads();
        As[lc + 0][lr] = a.x; As[lc + 1][lr] = a.y; As[lc + 2][lr] = a.z; As[lc + 3][lr] = a.w;
        Bs[lc + 0][lr] = b.x; Bs[lc + 1][lr] = b.y; Bs[lc + 2][lr] = b.z; Bs[lc + 3][lr] = b.w;
        __syncthreads();
        #pragma unroll
        for (int k = 0; k < 8; k++) {
            float4 a0 = *reinterpret_cast<const float4*>(&As[k][tm]);
            float4 a1 = *reinterpret_cast<const float4*>(&As[k][tm + 4]);
            float4 b0 = *reinterpret_cast<const float4*>(&Bs[k][tn]);
            float4 b1 = *reinterpret_cast<const float4*>(&Bs[k][tn + 4]);
            float ar[8] = {a0.x, a0.y, a0.z, a0.w, a1.x, a1.y, a1.z, a1.w};
            float br[8] = {b0.x, b0.y, b0.z, b0.w, b1.x, b1.y, b1.z, b1.w};
            #pragma unroll
            for (int i = 0; i < 8; i++)
                #pragma unroll
                for (int j = 0; j < 8; j++)
                    acc[i][j] = fmaf(ar[i], br[j], acc[i][j]);
        }
    }

    #pragma unroll
    for (int i = 0; i < 8; i++)
        #pragma unroll
        for (int j = 0; j < 8; j++)
            g_u[(size_t)(bm + tm + i) * RR + (bn + tn + j)] = acc[i][j] + bias[bn + tn + j];
}

// ---------------------------------------------------------------------------
// Persistent recurrence: fp16 weights + fp16 staged s + HFMA2 chunked dot.
// Block 512. 7 compute warps x 4 rows. Cols [0,C_SH) in SMEM (half),
// cols [C_SH,RR) register-resident (uint4 x2 per row per lane).
// ---------------------------------------------------------------------------
extern __shared__ unsigned char s_dyn[];

__global__ __launch_bounds__(TPB, 1) void recur_smem_kernel(int nctas)
{
    __half* wsh   = reinterpret_cast<__half*>(s_dyn);
    __half* s_shh = reinterpret_cast<__half*>(s_dyn + (size_t)ROWS_MAX * C_SH * 2);
    uint4*  s_sh4h = reinterpret_cast<uint4*>(s_shh);  // 8 halves per entry

    const int cta   = blockIdx.x;
    const int r0    = (cta * RR) / nctas;
    const int r1    = ((cta + 1) * RR) / nctas;
    const int nrows = r1 - r0;
    const int warp  = threadIdx.x >> 5;
    const int lane  = threadIdx.x & 31;
    const int tid   = threadIdx.x;

    // Prologue: copy resident weight block (cols [0,C_SH)) into SMEM
    {
        const int tot = nrows * C_SH8;
        uint4* wsh4 = reinterpret_cast<uint4*>(wsh);
        for (int idx = tid; idx < tot; idx += TPB) {
            int lrow = idx / C_SH8;
            int c8   = idx - lrow * C_SH8;
            wsh4[(size_t)lrow * C_SH8 + c8] =
                ldcg4u(reinterpret_cast<const uint4*>(g_wres_h + (size_t)(r0 + lrow) * RR) + c8);
        }
    }

    const int rowA   = r0 + 4 * warp;
    const bool active = (rowA < r1);
    bool rv[4];
    #pragma unroll
    for (int r = 0; r < 4; r++) rv[r] = active && (rowA + r < r1);

    // Register-resident tail weights (cols C_SH..RR-1), loaded ONCE.
    uint4 tw[4][RT8];
    #pragma unroll
    for (int r = 0; r < 4; r++)
        #pragma unroll
        for (int k = 0; k < RT8; k++) {
            if (rv[r]) {
                const uint4* wg = reinterpret_cast<const uint4*>(
                    g_wres_h + (size_t)(rowA + r) * RR + C_SH);
                tw[r][k] = ldcg4u(wg + lane + 32 * k);
            } else {
                tw[r][k] = make_uint4(0, 0, 0, 0);
            }
        }

    const uint4* ws4[4];
    #pragma unroll
    for (int r = 0; r < 4; r++)
        ws4[r] = reinterpret_cast<const uint4*>(wsh + (size_t)(4 * warp + r) * C_SH);

    // step 0: states[0] = tanh(u[0])
    if (tid < nrows) {
        int r = r0 + tid;
        g_states[r] = tanhf(ldcg(&g_u[r]));
    }
    unsigned bstep = 1;
    grid_barrier_step(nctas, bstep++);

    for (int t = 1; t < T_; ++t) {
        // Prefetch u[t] (independent of the barrier)
        float uval = 0.f;
        if (active && lane < 4 && rv[lane])
            uval = ldcg(&g_u[(size_t)t * RR + rowA + lane]);

        // Stage s_{t-1} into SMEM as HALF (each thread: 8 floats -> 8 halves)
        {
            const float4* sp4 = reinterpret_cast<const float4*>(
                g_states + (size_t)(t - 1) * RR);
            float4 a = ldcg4f(sp4 + 2 * tid);
            float4 b = ldcg4f(sp4 + 2 * tid + 1);
            uint4 o;
            __half2 h;
            h = __floats2half2_rn(a.x, a.y); o.x = *reinterpret_cast<uint32_t*>(&h);
            h = __floats2half2_rn(a.z, a.w); o.y = *reinterpret_cast<uint32_t*>(&h);
            h = __floats2half2_rn(b.x, b.y); o.z = *reinterpret_cast<uint32_t*>(&h);
            h = __floats2half2_rn(b.z, b.w); o.w = *reinterpret_cast<uint32_t*>(&h);
            s_sh4h[tid] = o;
        }
        __syncthreads();

        if (active) {
            float acc0 = 0.f, acc1 = 0.f, acc2 = 0.f, acc3 = 0.f;

            // SMEM-resident columns [0, C_SH): HFMA2 8-col chunks
            #pragma unroll 2
            for (int idx = lane; idx < C_SH8; idx += 32) {
                uint4 s8 = s_sh4h[idx];
                acc0 += dot8(ws4[0][idx], s8);
                acc1 += dot8(ws4[1][idx], s8);
                acc2 += dot8(ws4[2][idx], s8);
                acc3 += dot8(ws4[3][idx], s8);
            }
            // Register-resident tail [C_SH, RR)
            #pragma unroll
            for (int k = 0; k < RT8; k++) {
                uint4 s8 = s_sh4h[C_SH8 + lane + 32 * k];
                acc0 += dot8(tw[0][k], s8);
                acc1 += dot8(tw[1][k], s8);
                acc2 += dot8(tw[2][k], s8);
                acc3 += dot8(tw[3][k], s8);
            }

            #pragma unroll
            for (int o = 16; o; o >>= 1) {
                acc0 += __shfl_xor_sync(0xffffffffu, acc0, o);
                acc1 += __shfl_xor_sync(0xffffffffu, acc1, o);
                acc2 += __shfl_xor_sync(0xffffffffu, acc2, o);
                acc3 += __shfl_xor_sync(0xffffffffu, acc3, o);
            }
            if (lane < 4 && rv[lane]) {
                float sum = (lane == 0) ? acc0 :
                            (lane == 1) ? acc1 :
                            (lane == 2) ? acc2 : acc3;
                int row = rowA + lane;
                // leak uses exact fp32 previous state from gmem
                float sprev = ldcg(&g_states[(size_t)(t - 1) * RR + row]);
                float xi = tanhf(uval + sum);
                g_states[(size_t)t * RR + row] =
                    (1.0f - LEAK_) * sprev + LEAK_ * xi;
            }
        }
        grid_barrier_step(nctas, bstep++);
    }
}

// ---------------------------------------------------------------------------
// Streaming fallback (no dynamic SMEM). Always resident. (block 1024)
// ---------------------------------------------------------------------------
__global__ __launch_bounds__(1024, 1) void recur_fallback(int nctas)
{
    __shared__ float fs[RR];
    float4* fs4 = reinterpret_cast<float4*>(fs);

    const int cta   = blockIdx.x;
    const int r0    = (cta * RR) / nctas;
    const int r1    = ((cta + 1) * RR) / nctas;
    const int nrows = r1 - r0;
    const int warp  = threadIdx.x >> 5;
    const int lane  = threadIdx.x & 31;
    const int tid   = threadIdx.x;

    if (tid < nrows) {
        int r = r0 + tid;
        g_states[r] = tanhf(ldcg(&g_u[r]));
    }
    unsigned bstep = 1;
    grid_barrier_step(nctas, bstep++);

    const int npairs = (nrows + 1) >> 1;
    const int rowA = r0 + 2 * warp;
    const int rowB = rowA + 1;
    const bool active = (warp < npairs);
    const bool haveB  = active && (rowB < r1);

    const uint2* wgA = reinterpret_cast<const uint2*>(g_wres_h + (size_t)rowA * RR);
    const uint2* wgB = reinterpret_cast<const uint2*>(g_wres_h + (size_t)rowB * RR);

    for (int t = 1; t < T_; ++t) {
        float uA = 0.f, uB = 0.f;
        if (active && lane == 0) {
            uA = ldcg(&g_u[(size_t)t * RR + rowA]);
            if (haveB) uB = ldcg(&g_u[(size_t)t * RR + rowB]);
        }
        {
            const float4* sp4 = reinterpret_cast<const float4*>(
                g_states + (size_t)(t - 1) * RR);
            fs4[tid] = ldcg4f(sp4 + tid);
        }
        __syncthreads();

        if (active) {
            float accA = 0.f, accB = 0.f;
            #pragma unroll 8
            for (int idx = lane; idx < RR / 4; idx += 32) {
                float4 s = fs4[idx];
                fma4(ldcg2u(wgA + idx), s, accA);
                if (haveB) fma4(ldcg2u(wgB + idx), s, accB);
            }
            #pragma unroll
            for (int o = 16; o; o >>= 1) {
                accA += __shfl_xor_sync(0xffffffffu, accA, o);
                accB += __shfl_xor_sync(0xffffffffu, accB, o);
            }
            if (lane == 0) {
                float* scur = g_states + (size_t)t * RR;
                float xiA = tanhf(uA + accA);
                scur[rowA] = (1.0f - LEAK_) * fs[rowA] + LEAK_ * xiA;
                if (haveB) {
                    float xiB = tanhf(uB + accB);
                    scur[rowB] = (1.0f - LEAK_) * fs[rowB] + LEAK_ * xiB;
                }
            }
        }
        grid_barrier_step(nctas, bstep++);
    }
}

// ---------------------------------------------------------------------------
// GEMM 2: yout = concat(x, states) @ Wout^T + b
// ---------------------------------------------------------------------------
__global__ __launch_bounds__(256) void gemm_out_kernel(
    const float* __restrict__ x, const float* __restrict__ Wout,
    const float* __restrict__ bias, float* __restrict__ C)
{
    const int K = NINT;
    __shared__ float As[8][128];
    __shared__ float Bs[8][128];

    const int bm = blockIdx.y * 128;
    const int bn = blockIdx.x * 128;
    const int tid = threadIdx.x;
    const int tm = (tid >> 4) * 8;
    const int tn = (tid & 15) * 8;
    const int lr = tid >> 1;
    const int lc = (tid & 1) * 4;

    float acc[8][8];
    #pragma unroll
    for (int i = 0; i < 8; i++)
        #pragma unroll
        for (int j = 0; j < 8; j++) acc[i][j] = 0.f;

    for (int kb = 0; kb < K; kb += 8) {
        const int row = bm + lr;
        const int kk  = kb + lc;
        float4 a;
        if (kk < DIN)
            a = *reinterpret_cast<const float4*>(&x[(size_t)row * DIN + kk]);
        else
            a = *reinterpret_cast<const float4*>(&g_states[(size_t)row * RR + (kk - DIN)]);
        float4 b = *reinterpret_cast<const float4*>(&Wout[(size_t)(bn + lr) * K + kk]);
        __syncthreads();
        As[lc + 0][lr] = a.x; As[lc + 1][lr] = a.y; As[lc + 2][lr] = a.z; As[lc + 3][lr] = a.w;
        Bs[lc + 0][lr] = b.x; Bs[lc + 1][lr] = b.y; Bs[lc + 2][lr] = b.z; Bs[lc + 3][lr] = b.w;
        __syncthreads();
        #pragma unroll
        for (int k = 0; k < 8; k++) {
            float4 a0 = *reinterpret_cast<const float4*>(&As[k][tm]);
            float4 a1 = *reinterpret_cast<const float4*>(&As[k][tm + 4]);
            float4 b0 = *reinterpret_cast<const float4*>(&Bs[k][tn]);
            float4 b1 = *reinterpret_cast<const float4*>(&Bs[k][tn + 4]);
            float ar[8] = {a0.x, a0.y, a0.z, a0.w, a1.x, a1.y, a1.z, a1.w};
            float br[8] = {b0.x, b0.y, b0.z, b0.w, b1.x, b1.y, b1.z, b1.w};
            #pragma unroll
            for (int i = 0; i < 8; i++)
                #pragma unroll
                for (int j = 0; j < 8; j++)
                    acc[i][j] = fmaf(ar[i], br[j], acc[i][j]);
        }
    }

    #pragma unroll
    for (int i = 0; i < 8; i++)
        #pragma unroll
        for (int j = 0; j < 8; j++)
            C[(size_t)(bm + tm + i) * DOUT + (bn + tn + j)] = acc[i][j] + bias[bn + tn + j];
}

// ---------------------------------------------------------------------------
extern "C" void kernel_launch(void* const* d_in, const int* in_sizes, int n_in,
                              void* d_out, int out_size)
{
    const float* x      = (const float*)d_in[0];
    const float* Win_w  = (const float*)d_in[1];
    const float* Win_b  = (const float*)d_in[2];
    const float* Wres_w = (const float*)d_in[3];
    const float* Wout_w = (const float*)d_in[4];
    const float* Wout_b = (const float*)d_in[5];
    float* yout = (float*)d_out;

    int dev = 0;
    cudaGetDevice(&dev);
    int sms = 148;
    cudaDeviceGetAttribute(&sms, cudaDevAttrMultiProcessorCount, dev);
    if (sms < 64) sms = 64;
    if (sms > 256) sms = 256;

    cudaError_t attr_err = cudaFuncSetAttribute(
        recur_smem_kernel, cudaFuncAttributeMaxDynamicSharedMemorySize, (int)SMEM_BYTES);
    int nblk = 0;
    cudaError_t occ_err = cudaOccupancyMaxActiveBlocksPerMultiprocessor(
        &nblk, recur_smem_kernel, TPB, SMEM_BYTES);
    const int max_rows = (RR + sms - 1) / sms;
    const bool use_smem = (attr_err == cudaSuccess) &&
                          (occ_err == cudaSuccess) && (nblk >= 1) &&
                          (max_rows <= ROWS_MAX);

    reset_barrier_kernel<<<1, 32>>>();
    convert_wres_kernel<<<1024, 256>>>(Wres_w);

    dim3 g1(RR / 128, T_ / 128);
    gemm_u_kernel<<<g1, 256>>>(x, Win_w, Win_b);

    if (use_smem)
        recur_smem_kernel<<<sms, TPB, SMEM_BYTES>>>(sms);
    else
        recur_fallback<<<sms, 1024>>>(sms);

    dim3 g2(DOUT / 128, T_ / 128);
    gemm_out_kernel<<<g2, 256>>>(x, Wout_w, Wout_b, yout);

    (void)in_sizes; (void)n_in; (void)out_size;
}

// round 17
// speedup vs baseline: 1.2816x; 1.0094x over previous
#include <cuda_runtime.h>
#include <cuda_fp16.h>
#include <cstddef>
#include <cstdint>

// Problem constants (fixed shapes from reference)
#define T_    4096
#define DIN   512
#define RR    4096
#define DOUT  512
#define NINT  (RR + DIN)   // 4608
#define LEAK_ 0.9f

#define ROWS_MAX   28           // ceil(4096/148)
#define C_SH       3584         // half-cols of each row resident in SMEM
#define C_SH8      (C_SH / 8)   // 448 8-col chunks per row
#define RT8        2            // (RR-C_SH)/8/32 reg-tail uint4 per row per lane
#define SMEM_BYTES ((size_t)ROWS_MAX * C_SH * 2 + RR * 2)  // 200704+8192=208896

#define TPB        512          // block size for the recurrence

// ---------------------------------------------------------------------------
// Scratch (static __device__ arrays; runtime allocation is forbidden)
// ---------------------------------------------------------------------------
__device__ float  g_u[(size_t)T_ * RR];         // 64 MB
__device__ float  g_states[(size_t)T_ * RR];    // 64 MB fp32 states
__device__ __half g_states_h[(size_t)T_ * RR];  // 32 MB fp16 mirror (for staging)
__device__ __half g_wres_h[(size_t)RR * RR];    // 32 MB fp16 Wres

// Monotonic step barrier (R13-proven)
__device__ unsigned g_count = 0;
__device__ unsigned g_gen = 0;

__device__ __forceinline__ float ldcg(const float* p) { return __ldcg(p); }
__device__ __forceinline__ float4 ldcg4f(const float4* p) {
    float4 v;
    asm volatile("ld.global.cg.v4.f32 {%0,%1,%2,%3}, [%4];"
                 : "=f"(v.x), "=f"(v.y), "=f"(v.z), "=f"(v.w) : "l"(p));
    return v;
}
__device__ __forceinline__ uint4 ldcg4u(const uint4* p) {
    uint4 v;
    asm volatile("ld.global.cg.v4.u32 {%0,%1,%2,%3}, [%4];"
                 : "=r"(v.x), "=r"(v.y), "=r"(v.z), "=r"(v.w) : "l"(p));
    return v;
}
__device__ __forceinline__ uint2 ldcg2u(const uint2* p) {
    uint2 v;
    asm volatile("ld.global.cg.v2.u32 {%0,%1}, [%2];"
                 : "=r"(v.x), "=r"(v.y) : "l"(p));
    return v;
}

__device__ __forceinline__ float2 h2f(uint32_t h)
{
    return __half22float2(*reinterpret_cast<const __half2*>(&h));
}

// 8-col fp16 dot: half2 chain (4 HFMA2-class ops), flushed to fp32.
__device__ __forceinline__ float dot8(uint4 w, uint4 s)
{
    const __half2* wh = reinterpret_cast<const __half2*>(&w);
    const __half2* sh = reinterpret_cast<const __half2*>(&s);
    __half2 acc = __hmul2(wh[0], sh[0]);
    acc = __hfma2(wh[1], sh[1], acc);
    acc = __hfma2(wh[2], sh[2], acc);
    acc = __hfma2(wh[3], sh[3], acc);
    float2 f = __half22float2(acc);
    return f.x + f.y;
}

// 4 halves (uint2) * float4 -> acc (fallback kernel)
__device__ __forceinline__ void fma4(uint2 w, float4 s, float& acc)
{
    float2 f0 = h2f(w.x);
    float2 f1 = h2f(w.y);
    acc = fmaf(f0.x, s.x, acc); acc = fmaf(f0.y, s.y, acc);
    acc = fmaf(f1.x, s.z, acc); acc = fmaf(f1.y, s.w, acc);
}

// ---------------------------------------------------------------------------
// Monotonic scoped-atomic grid barrier with fast-path poll.
// ---------------------------------------------------------------------------
__device__ __forceinline__ void grid_barrier_step(int nctas, unsigned step)
{
    __syncthreads();
    if (threadIdx.x == 0) {
        unsigned old;
        asm volatile("atom.add.release.gpu.u32 %0, [%1], 1;"
                     : "=r"(old) : "l"(&g_count) : "memory");
        if (old + 1u == step * (unsigned)nctas) {
            asm volatile("st.release.gpu.u32 [%0], %1;"
                         :: "l"(&g_gen), "r"(step) : "memory");
        }
        unsigned cur;
        asm volatile("ld.acquire.gpu.u32 %0, [%1];"
                     : "=r"(cur) : "l"(&g_gen) : "memory");
        while (cur < step) {
            __nanosleep(20);
            asm volatile("ld.acquire.gpu.u32 %0, [%1];"
                         : "=r"(cur) : "l"(&g_gen) : "memory");
        }
    }
    __syncthreads();
}

__global__ void reset_barrier_kernel()
{
    if (threadIdx.x == 0) { g_count = 0; g_gen = 0; }
}

// ---------------------------------------------------------------------------
// Convert Wres fp32 -> fp16 (once per launch)
// ---------------------------------------------------------------------------
__global__ __launch_bounds__(256) void convert_wres_kernel(const float* __restrict__ W)
{
    const size_t n8 = (size_t)RR * RR / 8;
    uint4* out = reinterpret_cast<uint4*>(g_wres_h);
    const float4* in = reinterpret_cast<const float4*>(W);
    for (size_t k = (size_t)blockIdx.x * blockDim.x + threadIdx.x;
         k < n8; k += (size_t)gridDim.x * blockDim.x) {
        float4 a = ldcg4f(in + 2 * k);
        float4 b = ldcg4f(in + 2 * k + 1);
        uint4 o;
        __half2 h;
        h = __floats2half2_rn(a.x, a.y); o.x = *reinterpret_cast<uint32_t*>(&h);
        h = __floats2half2_rn(a.z, a.w); o.y = *reinterpret_cast<uint32_t*>(&h);
        h = __floats2half2_rn(b.x, b.y); o.z = *reinterpret_cast<uint32_t*>(&h);
        h = __floats2half2_rn(b.z, b.w); o.w = *reinterpret_cast<uint32_t*>(&h);
        out[k] = o;
    }
}

// ---------------------------------------------------------------------------
// GEMM 1: g_u[t][r] = sum_d x[t,d] * Win_w[r,d] + Win_b[r]
// ---------------------------------------------------------------------------
__global__ __launch_bounds__(256) void gemm_u_kernel(
    const float* __restrict__ A, const float* __restrict__ B,
    const float* __restrict__ bias)
{
    const int K = DIN;
    __shared__ float As[8][128];
    __shared__ float Bs[8][128];

    const int bm = blockIdx.y * 128;
    const int bn = blockIdx.x * 128;
    const int tid = threadIdx.x;
    const int tm = (tid >> 4) * 8;
    const int tn = (tid & 15) * 8;
    const int lr = tid >> 1;
    const int lc = (tid & 1) * 4;

    float acc[8][8];
    #pragma unroll
    for (int i = 0; i < 8; i++)
        #pragma unroll
        for (int j = 0; j < 8; j++) acc[i][j] = 0.f;

    for (int kb = 0; kb < K; kb += 8) {
        float4 a = *reinterpret_cast<const float4*>(&A[(size_t)(bm + lr) * K + kb + lc]);
        float4 b = *reinterpret_cast<const float4*>(&B[(size_t)(bn + lr) * K + kb + lc]);
        __syncthreads();
        As[lc + 0][lr] = a.x; As[lc + 1][lr] = a.y; As[lc + 2][lr] = a.z; As[lc + 3][lr] = a.w;
        Bs[lc + 0][lr] = b.x; Bs[lc + 1][lr] = b.y; Bs[lc + 2][lr] = b.z; Bs[lc + 3][lr] = b.w;
        __syncthreads();
        #pragma unroll
        for (int k = 0; k < 8; k++) {
            float4 a0 = *reinterpret_cast<const float4*>(&As[k][tm]);
            float4 a1 = *reinterpret_cast<const float4*>(&As[k][tm + 4]);
            float4 b0 = *reinterpret_cast<const float4*>(&Bs[k][tn]);
            float4 b1 = *reinterpret_cast<const float4*>(&Bs[k][tn + 4]);
            float ar[8] = {a0.x, a0.y, a0.z, a0.w, a1.x, a1.y, a1.z, a1.w};
            float br[8] = {b0.x, b0.y, b0.z, b0.w, b1.x, b1.y, b1.z, b1.w};
            #pragma unroll
            for (int i = 0; i < 8; i++)
                #pragma unroll
                for (int j = 0; j < 8; j++)
                    acc[i][j] = fmaf(ar[i], br[j], acc[i][j]);
        }
    }

    #pragma unroll
    for (int i = 0; i < 8; i++)
        #pragma unroll
        for (int j = 0; j < 8; j++)
            g_u[(size_t)(bm + tm + i) * RR + (bn + tn + j)] = acc[i][j] + bias[bn + tn + j];
}

// ---------------------------------------------------------------------------
// Persistent recurrence: fp16 weights + fp16 state mirror + HFMA2 dot.
// Block 512. 7 compute warps x 4 rows. Cols [0,C_SH) in SMEM (half),
// cols [C_SH,RR) register-resident. Staging reads the fp16 mirror directly.
// ---------------------------------------------------------------------------
extern __shared__ unsigned char s_dyn[];

__global__ __launch_bounds__(TPB, 1) void recur_smem_kernel(int nctas)
{
    __half* wsh   = reinterpret_cast<__half*>(s_dyn);
    __half* s_shh = reinterpret_cast<__half*>(s_dyn + (size_t)ROWS_MAX * C_SH * 2);
    uint4*  s_sh4h = reinterpret_cast<uint4*>(s_shh);  // 8 halves per entry

    const int cta   = blockIdx.x;
    const int r0    = (cta * RR) / nctas;
    const int r1    = ((cta + 1) * RR) / nctas;
    const int nrows = r1 - r0;
    const int warp  = threadIdx.x >> 5;
    const int lane  = threadIdx.x & 31;
    const int tid   = threadIdx.x;

    // Prologue: copy resident weight block (cols [0,C_SH)) into SMEM
    {
        const int tot = nrows * C_SH8;
        uint4* wsh4 = reinterpret_cast<uint4*>(wsh);
        for (int idx = tid; idx < tot; idx += TPB) {
            int lrow = idx / C_SH8;
            int c8   = idx - lrow * C_SH8;
            wsh4[(size_t)lrow * C_SH8 + c8] =
                ldcg4u(reinterpret_cast<const uint4*>(g_wres_h + (size_t)(r0 + lrow) * RR) + c8);
        }
    }

    const int rowA   = r0 + 4 * warp;
    const bool active = (rowA < r1);
    bool rv[4];
    #pragma unroll
    for (int r = 0; r < 4; r++) rv[r] = active && (rowA + r < r1);

    // Register-resident tail weights (cols C_SH..RR-1), loaded ONCE.
    uint4 tw[4][RT8];
    #pragma unroll
    for (int r = 0; r < 4; r++)
        #pragma unroll
        for (int k = 0; k < RT8; k++) {
            if (rv[r]) {
                const uint4* wg = reinterpret_cast<const uint4*>(
                    g_wres_h + (size_t)(rowA + r) * RR + C_SH);
                tw[r][k] = ldcg4u(wg + lane + 32 * k);
            } else {
                tw[r][k] = make_uint4(0, 0, 0, 0);
            }
        }

    const uint4* ws4[4];
    #pragma unroll
    for (int r = 0; r < 4; r++)
        ws4[r] = reinterpret_cast<const uint4*>(wsh + (size_t)(4 * warp + r) * C_SH);

    // step 0: states[0] = tanh(u[0]) (fp32 + fp16 mirror)
    if (tid < nrows) {
        int r = r0 + tid;
        float s0 = tanhf(ldcg(&g_u[r]));
        g_states[r]   = s0;
        g_states_h[r] = __float2half_rn(s0);
    }
    unsigned bstep = 1;
    grid_barrier_step(nctas, bstep++);

    for (int t = 1; t < T_; ++t) {
        // Prefetch u[t] (independent of the barrier)
        float uval = 0.f;
        if (active && lane < 4 && rv[lane])
            uval = ldcg(&g_u[(size_t)t * RR + rowA + lane]);

        // Stage s_{t-1}: one 16B load of 8 halves per thread from the mirror
        s_sh4h[tid] = ldcg4u(
            reinterpret_cast<const uint4*>(g_states_h + (size_t)(t - 1) * RR) + tid);
        __syncthreads();

        // Early sprev (fp32, exact) — issued ~1us before use
        float sprev = 0.f;
        if (active && lane < 4 && rv[lane])
            sprev = ldcg(&g_states[(size_t)(t - 1) * RR + rowA + lane]);

        if (active) {
            float acc0 = 0.f, acc1 = 0.f, acc2 = 0.f, acc3 = 0.f;

            #pragma unroll 2
            for (int idx = lane; idx < C_SH8; idx += 32) {
                uint4 s8 = s_sh4h[idx];
                acc0 += dot8(ws4[0][idx], s8);
                acc1 += dot8(ws4[1][idx], s8);
                acc2 += dot8(ws4[2][idx], s8);
                acc3 += dot8(ws4[3][idx], s8);
            }
            #pragma unroll
            for (int k = 0; k < RT8; k++) {
                uint4 s8 = s_sh4h[C_SH8 + lane + 32 * k];
                acc0 += dot8(tw[0][k], s8);
                acc1 += dot8(tw[1][k], s8);
                acc2 += dot8(tw[2][k], s8);
                acc3 += dot8(tw[3][k], s8);
            }

            #pragma unroll
            for (int o = 16; o; o >>= 1) {
                acc0 += __shfl_xor_sync(0xffffffffu, acc0, o);
                acc1 += __shfl_xor_sync(0xffffffffu, acc1, o);
                acc2 += __shfl_xor_sync(0xffffffffu, acc2, o);
                acc3 += __shfl_xor_sync(0xffffffffu, acc3, o);
            }
            if (lane < 4 && rv[lane]) {
                float sum = (lane == 0) ? acc0 :
                            (lane == 1) ? acc1 :
                            (lane == 2) ? acc2 : acc3;
                int row = rowA + lane;
                float xi = tanhf(uval + sum);
                float snew = (1.0f - LEAK_) * sprev + LEAK_ * xi;
                g_states[(size_t)t * RR + row]   = snew;
                g_states_h[(size_t)t * RR + row] = __float2half_rn(snew);
            }
        }
        grid_barrier_step(nctas, bstep++);
    }
}

// ---------------------------------------------------------------------------
// Streaming fallback (no dynamic SMEM). Always resident. (block 1024)
// ---------------------------------------------------------------------------
__global__ __launch_bounds__(1024, 1) void recur_fallback(int nctas)
{
    __shared__ float fs[RR];
    float4* fs4 = reinterpret_cast<float4*>(fs);

    const int cta   = blockIdx.x;
    const int r0    = (cta * RR) / nctas;
    const int r1    = ((cta + 1) * RR) / nctas;
    const int nrows = r1 - r0;
    const int warp  = threadIdx.x >> 5;
    const int lane  = threadIdx.x & 31;
    const int tid   = threadIdx.x;

    if (tid < nrows) {
        int r = r0 + tid;
        g_states[r] = tanhf(ldcg(&g_u[r]));
    }
    unsigned bstep = 1;
    grid_barrier_step(nctas, bstep++);

    const int npairs = (nrows + 1) >> 1;
    const int rowA = r0 + 2 * warp;
    const int rowB = rowA + 1;
    const bool active = (warp < npairs);
    const bool haveB  = active && (rowB < r1);

    const uint2* wgA = reinterpret_cast<const uint2*>(g_wres_h + (size_t)rowA * RR);
    const uint2* wgB = reinterpret_cast<const uint2*>(g_wres_h + (size_t)rowB * RR);

    for (int t = 1; t < T_; ++t) {
        float uA = 0.f, uB = 0.f;
        if (active && lane == 0) {
            uA = ldcg(&g_u[(size_t)t * RR + rowA]);
            if (haveB) uB = ldcg(&g_u[(size_t)t * RR + rowB]);
        }
        {
            const float4* sp4 = reinterpret_cast<const float4*>(
                g_states + (size_t)(t - 1) * RR);
            fs4[tid] = ldcg4f(sp4 + tid);
        }
        __syncthreads();

        if (active) {
            float accA = 0.f, accB = 0.f;
            #pragma unroll 8
            for (int idx = lane; idx < RR / 4; idx += 32) {
                float4 s = fs4[idx];
                fma4(ldcg2u(wgA + idx), s, accA);
                if (haveB) fma4(ldcg2u(wgB + idx), s, accB);
            }
            #pragma unroll
            for (int o = 16; o; o >>= 1) {
                accA += __shfl_xor_sync(0xffffffffu, accA, o);
                accB += __shfl_xor_sync(0xffffffffu, accB, o);
            }
            if (lane == 0) {
                float* scur = g_states + (size_t)t * RR;
                float xiA = tanhf(uA + accA);
                scur[rowA] = (1.0f - LEAK_) * fs[rowA] + LEAK_ * xiA;
                if (haveB) {
                    float xiB = tanhf(uB + accB);
                    scur[rowB] = (1.0f - LEAK_) * fs[rowB] + LEAK_ * xiB;
                }
            }
        }
        grid_barrier_step(nctas, bstep++);
    }
}

// ---------------------------------------------------------------------------
// GEMM 2: yout = concat(x, states) @ Wout^T + b
// ---------------------------------------------------------------------------
__global__ __launch_bounds__(256) void gemm_out_kernel(
    const float* __restrict__ x, const float* __restrict__ Wout,
    const float* __restrict__ bias, float* __restrict__ C)
{
    const int K = NINT;
    __shared__ float As[8][128];
    __shared__ float Bs[8][128];

    const int bm = blockIdx.y * 128;
    const int bn = blockIdx.x * 128;
    const int tid = threadIdx.x;
    const int tm = (tid >> 4) * 8;
    const int tn = (tid & 15) * 8;
    const int lr = tid >> 1;
    const int lc = (tid & 1) * 4;

    float acc[8][8];
    #pragma unroll
    for (int i = 0; i < 8; i++)
        #pragma unroll
        for (int j = 0; j < 8; j++) acc[i][j] = 0.f;

    for (int kb = 0; kb < K; kb += 8) {
        const int row = bm + lr;
        const int kk  = kb + lc;
        float4 a;
        if (kk < DIN)
            a = *reinterpret_cast<const float4*>(&x[(size_t)row * DIN + kk]);
        else
            a = *reinterpret_cast<const float4*>(&g_states[(size_t)row * RR + (kk - DIN)]);
        float4 b = *reinterpret_cast<const float4*>(&Wout[(size_t)(bn + lr) * K + kk]);
        __syncthreads();
        As[lc + 0][lr] = a.x; As[lc + 1][lr] = a.y; As[lc + 2][lr] = a.z; As[lc + 3][lr] = a.w;
        Bs[lc + 0][lr] = b.x; Bs[lc + 1][lr] = b.y; Bs[lc + 2][lr] = b.z; Bs[lc + 3][lr] = b.w;
        __syncthreads();
        #pragma unroll
        for (int k = 0; k < 8; k++) {
            float4 a0 = *reinterpret_cast<const float4*>(&As[k][tm]);
            float4 a1 = *reinterpret_cast<const float4*>(&As[k][tm + 4]);
            float4 b0 = *reinterpret_cast<const float4*>(&Bs[k][tn]);
            float4 b1 = *reinterpret_cast<const float4*>(&Bs[k][tn + 4]);
            float ar[8] = {a0.x, a0.y, a0.z, a0.w, a1.x, a1.y, a1.z, a1.w};
            float br[8] = {b0.x, b0.y, b0.z, b0.w, b1.x, b1.y, b1.z, b1.w};
            #pragma unroll
            for (int i = 0; i < 8; i++)
                #pragma unroll
                for (int j = 0; j < 8; j++)
                    acc[i][j] = fmaf(ar[i], br[j], acc[i][j]);
        }
    }

    #pragma unroll
    for (int i = 0; i < 8; i++)
        #pragma unroll
        for (int j = 0; j < 8; j++)
            C[(size_t)(bm + tm + i) * DOUT + (bn + tn + j)] = acc[i][j] + bias[bn + tn + j];
}

// ---------------------------------------------------------------------------
extern "C" void kernel_launch(void* const* d_in, const int* in_sizes, int n_in,
                              void* d_out, int out_size)
{
    const float* x      = (const float*)d_in[0];
    const float* Win_w  = (const float*)d_in[1];
    const float* Win_b  = (const float*)d_in[2];
    const float* Wres_w = (const float*)d_in[3];
    const float* Wout_w = (const float*)d_in[4];
    const float* Wout_b = (const float*)d_in[5];
    float* yout = (float*)d_out;

    int dev = 0;
    cudaGetDevice(&dev);
    int sms = 148;
    cudaDeviceGetAttribute(&sms, cudaDevAttrMultiProcessorCount, dev);
    if (sms < 64) sms = 64;
    if (sms > 256) sms = 256;

    cudaError_t attr_err = cudaFuncSetAttribute(
        recur_smem_kernel, cudaFuncAttributeMaxDynamicSharedMemorySize, (int)SMEM_BYTES);
    int nblk = 0;
    cudaError_t occ_err = cudaOccupancyMaxActiveBlocksPerMultiprocessor(
        &nblk, recur_smem_kernel, TPB, SMEM_BYTES);
    const int max_rows = (RR + sms - 1) / sms;
    const bool use_smem = (attr_err == cudaSuccess) &&
                          (occ_err == cudaSuccess) && (nblk >= 1) &&
                          (max_rows <= ROWS_MAX);

    reset_barrier_kernel<<<1, 32>>>();
    convert_wres_kernel<<<1024, 256>>>(Wres_w);

    dim3 g1(RR / 128, T_ / 128);
    gemm_u_kernel<<<g1, 256>>>(x, Win_w, Win_b);

    if (use_smem)
        recur_smem_kernel<<<sms, TPB, SMEM_BYTES>>>(sms);
    else
        recur_fallback<<<sms, 1024>>>(sms);

    dim3 g2(DOUT / 128, T_ / 128);
    gemm_out_kernel<<<g2, 256>>>(x, Wout_w, Wout_b, yout);

    (void)in_sizes; (void)n_in; (void)out_size;
}